// round 12
// baseline (speedup 1.0000x reference)
#include <cuda_runtime.h>
#include <cuda_fp16.h>
#include <math.h>
#include <stdint.h>

#define BB 2
#define SS 2048
#define DD 768
#define HH 12
#define DKK 64
#define DFF 3072
#define MROWS (BB*SS)   // 4096

// ---------------- scratch (device globals: allocation-free) ----------------
__device__ __half h_ln1 [MROWS*DD];
__device__ __half h_q   [MROWS*DD];
__device__ __half h_k   [MROWS*DD];
__device__ __half h_v   [MROWS*DD];
__device__ __half h_attn[MROWS*DD];
__device__ float  g_x1  [MROWS*DD];
__device__ __half h_ln2 [MROWS*DD];
__device__ __half h_ffn1[MROWS*DFF];
// transposed half weights: Wt[N][K]
__device__ __half h_wq[DD*DD];
__device__ __half h_wk[DD*DD];
__device__ __half h_wv[DD*DD];
__device__ __half h_wo[DD*DD];
__device__ __half h_w1[DD*DFF];
__device__ __half h_w2[DFF*DD];

// ---------------- helpers ----------------
__device__ __forceinline__ float gelu_exact(float v) {
    return 0.5f * v * (1.0f + erff(v * 0.70710678118654752f));
}
__device__ __forceinline__ void cp_async16(void* smem, const void* gmem) {
    uint32_t s = (uint32_t)__cvta_generic_to_shared(smem);
    asm volatile("cp.async.cg.shared.global [%0], [%1], 16;\n" :: "r"(s), "l"(gmem));
}
#define CP_COMMIT() asm volatile("cp.async.commit_group;\n" ::)
#define CP_WAIT(n)  asm volatile("cp.async.wait_group %0;\n" :: "n"(n))

__device__ __forceinline__ void mma_f16(float* c, const uint32_t* a, uint32_t b0, uint32_t b1) {
    asm volatile(
      "mma.sync.aligned.m16n8k16.row.col.f32.f16.f16.f32 "
      "{%0,%1,%2,%3}, {%4,%5,%6,%7}, {%8,%9}, {%0,%1,%2,%3};\n"
      : "+f"(c[0]), "+f"(c[1]), "+f"(c[2]), "+f"(c[3])
      : "r"(a[0]), "r"(a[1]), "r"(a[2]), "r"(a[3]), "r"(b0), "r"(b1));
}
__device__ __forceinline__ void ldsm_x4(uint32_t& r0, uint32_t& r1, uint32_t& r2, uint32_t& r3,
                                        uint32_t addr) {
    asm volatile("ldmatrix.sync.aligned.m8n8.x4.shared.b16 {%0,%1,%2,%3}, [%4];\n"
      : "=r"(r0), "=r"(r1), "=r"(r2), "=r"(r3) : "r"(addr));
}
__device__ __forceinline__ void ldsm_x4_t(uint32_t& r0, uint32_t& r1, uint32_t& r2, uint32_t& r3,
                                          uint32_t addr) {
    asm volatile("ldmatrix.sync.aligned.m8n8.x4.trans.shared.b16 {%0,%1,%2,%3}, [%4];\n"
      : "=r"(r0), "=r"(r1), "=r"(r2), "=r"(r3) : "r"(addr));
}

// ---------------- fused prep: 6 weight transposes + LN1, one launch --------
__global__ void __launch_bounds__(256)
prep_kernel(const float* __restrict__ wq, const float* __restrict__ wk,
            const float* __restrict__ wv, const float* __restrict__ wo,
            const float* __restrict__ w1, const float* __restrict__ w2,
            __half* __restrict__ twq, __half* __restrict__ twk,
            __half* __restrict__ twv, __half* __restrict__ two,
            __half* __restrict__ tw1, __half* __restrict__ tw2,
            const float* __restrict__ x, const float* __restrict__ gamma,
            const float* __restrict__ beta, __half* __restrict__ lnout)
{
    __shared__ float sb[32*33];
    const int idx = blockIdx.x;
    const int tid = threadIdx.x;

    if (idx < 6912) {
        const float* W; __half* Wt; int K, N, tk, tn;
        if (idx < 2304) {
            const int which = idx / 576, r = idx % 576;
            W  = (which == 0) ? wq  : (which == 1) ? wk  : (which == 2) ? wv  : wo;
            Wt = (which == 0) ? twq : (which == 1) ? twk : (which == 2) ? twv : two;
            K = DD; N = DD; tk = r % 24; tn = r / 24;
        } else if (idx < 4608) {
            const int r = idx - 2304;
            W = w1; Wt = tw1; K = DD; N = DFF; tk = r % 24; tn = r / 24;
        } else {
            const int r = idx - 4608;
            W = w2; Wt = tw2; K = DFF; N = DD; tk = r % 96; tn = r / 96;
        }
        const int k0 = tk * 32, n0 = tn * 32;
        const int tx = tid & 31, ty = tid >> 5;       // 32 x 8
        #pragma unroll
        for (int i = 0; i < 32; i += 8)
            sb[(ty + i) * 33 + tx] = W[(size_t)(k0 + ty + i) * N + n0 + tx];
        __syncthreads();
        #pragma unroll
        for (int i = 0; i < 32; i += 8)
            Wt[(size_t)(n0 + ty + i) * K + k0 + tx] = __float2half_rn(sb[tx * 33 + ty + i]);
    } else {
        const int row = idx - 6912;
        const float* xr = x + (size_t)row * DD;
        float a = xr[tid], b = xr[tid + 256], c = xr[tid + 512];
        float s  = a + b + c;
        float ss = a*a + b*b + c*c;
        #pragma unroll
        for (int off = 16; off > 0; off >>= 1) {
            s  += __shfl_xor_sync(0xffffffffu, s,  off);
            ss += __shfl_xor_sync(0xffffffffu, ss, off);
        }
        int wid = tid >> 5, lane = tid & 31;
        if (lane == 0) { sb[wid] = s; sb[8 + wid] = ss; }
        __syncthreads();
        float tot = 0.f, tot2 = 0.f;
        #pragma unroll
        for (int i = 0; i < 8; i++) { tot += sb[i]; tot2 += sb[8 + i]; }
        float mean = tot * (1.0f / DD);
        float var  = tot2 * (1.0f / DD) - mean * mean;
        float rstd = rsqrtf(var + 1e-7f);
        __half* orow = lnout + (size_t)row * DD;
        orow[tid      ] = __float2half_rn(gamma[tid      ] * (a - mean) * rstd + beta[tid      ]);
        orow[tid + 256] = __float2half_rn(gamma[tid + 256] * (b - mean) * rstd + beta[tid + 256]);
        orow[tid + 512] = __float2half_rn(gamma[tid + 512] * (c - mean) * rstd + beta[tid + 512]);
    }
}

// ---------------- LayerNorm (standalone, for LN2) ----------------
__global__ void ln_kernel(const float* __restrict__ x,
                          const float* __restrict__ gamma,
                          const float* __restrict__ beta,
                          __half* __restrict__ out)
{
    int row = blockIdx.x;
    const float* xr = x + (size_t)row * DD;
    int tid = threadIdx.x;

    float a = xr[tid], b = xr[tid + 256], c = xr[tid + 512];
    float s  = a + b + c;
    float ss = a*a + b*b + c*c;
    #pragma unroll
    for (int off = 16; off > 0; off >>= 1) {
        s  += __shfl_xor_sync(0xffffffffu, s,  off);
        ss += __shfl_xor_sync(0xffffffffu, ss, off);
    }
    __shared__ float sh0[8], sh1[8];
    int wid = tid >> 5, lane = tid & 31;
    if (lane == 0) { sh0[wid] = s; sh1[wid] = ss; }
    __syncthreads();
    float tot = 0.f, tot2 = 0.f;
    #pragma unroll
    for (int i = 0; i < 8; i++) { tot += sh0[i]; tot2 += sh1[i]; }
    float mean = tot * (1.0f / DD);
    float var  = tot2 * (1.0f / DD) - mean * mean;
    float rstd = rsqrtf(var + 1e-7f);

    __half* orow = out + (size_t)row * DD;
    orow[tid      ] = __float2half_rn(gamma[tid      ] * (a - mean) * rstd + beta[tid      ]);
    orow[tid + 256] = __float2half_rn(gamma[tid + 256] * (b - mean) * rstd + beta[tid + 256]);
    orow[tid + 512] = __float2half_rn(gamma[tid + 512] * (c - mean) * rstd + beta[tid + 512]);
}

// ---------------- fp16 tensor-core GEMM: 5-stage ring, distance 3 ---------
// C[M,N] = A[M,K](f16) @ Wt[N,K](f16)^T + bias(f32)
// CTA 128x64, BK=32, 4 warps (2x2), warp tile 64x32, 5-stage cp.async ring.
// Per iter: load(it+3) -> commit -> wait(3) -> sync -> compute. One barrier.
// EPI: 0 = bias -> half | 1 = bias + resid -> f32 | 2 = bias + GELU -> half
#define STAGE_BYTES 15360            // As 128x40x2 (10240) + Bs 64x40x2 (5120)
#define GSTAGES 5
#define GSMEM (GSTAGES*STAGE_BYTES)  // 76,800 B

template<int EPI>
__device__ __forceinline__ void hgemm_body(
    const __half* __restrict__ A, const __half* __restrict__ Wt,
    const float* __restrict__ bias, const float* __restrict__ resid,
    void* __restrict__ Cv, int K, int N)
{
    extern __shared__ __align__(16) char dsm[];

    const int tid  = threadIdx.x;
    const int wid  = tid >> 5;
    const int lane = tid & 31;
    const int lr   = lane >> 2;
    const int lc   = lane & 3;
    const int wm   = wid >> 1;        // 0..1
    const int wn   = wid & 1;         // 0..1

    const int rowBase = blockIdx.y * 128;
    const int colBase = blockIdx.x * 64;

    float acc[4][4][4];
    #pragma unroll
    for (int i = 0; i < 4; i++)
        #pragma unroll
        for (int j = 0; j < 4; j++)
            #pragma unroll
            for (int q = 0; q < 4; q++) acc[i][j][q] = 0.f;

    auto load_tiles = [&](int st, int k0) {
        __half (*As)[40] = (__half(*)[40])(dsm + st * STAGE_BYTES);
        __half (*Bs)[40] = (__half(*)[40])(dsm + st * STAGE_BYTES + 10240);
        #pragma unroll
        for (int i = 0; i < 4; i++) {
            int c = tid + i * 128;          // 0..511 -> A 128 rows x 4 chunks
            int r = c >> 2, ko = (c & 3) * 8;
            cp_async16(&As[r][ko], A + (size_t)(rowBase + r) * K + k0 + ko);
        }
        #pragma unroll
        for (int i = 0; i < 2; i++) {
            int c = tid + i * 128;          // 0..255 -> B 64 rows x 4 chunks
            int r = c >> 2, ko = (c & 3) * 8;
            cp_async16(&Bs[r][ko], Wt + (size_t)(colBase + r) * K + k0 + ko);
        }
    };

    const int g = lane >> 3;
    const int grow = lane & 7;
    const int aRowOff = ((g & 1) * 8 + grow);
    const int aColOff = (g >> 1) * 8;
    const int bRowOff = ((g >> 1) * 8 + grow);
    const int bColOff = (g & 1) * 8;

    const int niter = K >> 5;                  // >= 24
    load_tiles(0, 0);  CP_COMMIT();
    load_tiles(1, 32); CP_COMMIT();
    load_tiles(2, 64); CP_COMMIT();

    int st = 0, pst = 3;                       // current stage, prefetch stage
    for (int it = 0; it < niter; it++) {
        const int rem = niter - 1 - it;        // groups still outstanding beyond current
        if (it + 3 < niter) {
            load_tiles(pst, (it + 3) << 5);
            CP_COMMIT();
            if (++pst == GSTAGES) pst = 0;
            CP_WAIT(3);
        } else if (rem >= 2) {
            CP_WAIT(2);
        } else if (rem == 1) {
            CP_WAIT(1);
        } else {
            CP_WAIT(0);
        }
        __syncthreads();

        __half (*As)[40] = (__half(*)[40])(dsm + st * STAGE_BYTES);
        __half (*Bs)[40] = (__half(*)[40])(dsm + st * STAGE_BYTES + 10240);
        #pragma unroll
        for (int kc = 0; kc < 2; kc++) {
            const int kk = kc * 16;
            uint32_t bf[4][2];
            #pragma unroll
            for (int jp = 0; jp < 2; jp++) {
                const int n = wn * 32 + jp * 16 + bRowOff;
                uint32_t addr = (uint32_t)__cvta_generic_to_shared(&Bs[n][kk + bColOff]);
                ldsm_x4(bf[2*jp][0], bf[2*jp][1], bf[2*jp+1][0], bf[2*jp+1][1], addr);
            }
            #pragma unroll
            for (int i = 0; i < 4; i++) {
                const int m = wm * 64 + i * 16;
                uint32_t a[4];
                uint32_t addr = (uint32_t)__cvta_generic_to_shared(&As[m + aRowOff][kk + aColOff]);
                ldsm_x4(a[0], a[1], a[2], a[3], addr);
                #pragma unroll
                for (int j = 0; j < 4; j++) mma_f16(acc[i][j], a, bf[j][0], bf[j][1]);
            }
        }
        __syncthreads();      // WAR: stage st may be prefetch target in 2 iters
        if (++st == GSTAGES) st = 0;
    }

    const int row0 = rowBase + wm * 64;
    const int col0 = colBase + wn * 32;
    __half* Ch = (__half*)Cv;
    float*  Cf = (float*)Cv;
    #pragma unroll
    for (int j = 0; j < 4; j++) {
        const int col = col0 + j * 8 + lc * 2;
        const float b0v = bias[col], b1v = bias[col + 1];
        #pragma unroll
        for (int i = 0; i < 4; i++) {
            const int r0 = row0 + i * 16 + lr;
            float v0 = acc[i][j][0] + b0v;
            float v1 = acc[i][j][1] + b1v;
            float v2 = acc[i][j][2] + b0v;
            float v3 = acc[i][j][3] + b1v;
            if (EPI == 1) {
                v0 += resid[(size_t)r0 * N + col];
                v1 += resid[(size_t)r0 * N + col + 1];
                v2 += resid[(size_t)(r0 + 8) * N + col];
                v3 += resid[(size_t)(r0 + 8) * N + col + 1];
                *(float2*)&Cf[(size_t)r0 * N + col]       = make_float2(v0, v1);
                *(float2*)&Cf[(size_t)(r0 + 8) * N + col] = make_float2(v2, v3);
            } else {
                if (EPI == 2) {
                    v0 = gelu_exact(v0); v1 = gelu_exact(v1);
                    v2 = gelu_exact(v2); v3 = gelu_exact(v3);
                }
                *(__half2*)&Ch[(size_t)r0 * N + col]       = __floats2half2_rn(v0, v1);
                *(__half2*)&Ch[(size_t)(r0 + 8) * N + col] = __floats2half2_rn(v2, v3);
            }
        }
    }
}

template<int EPI>
__global__ void __launch_bounds__(128, 2)
hgemm(const __half* __restrict__ A, const __half* __restrict__ Wt,
      const float* __restrict__ bias, const float* __restrict__ resid,
      void* __restrict__ C, int K, int N)
{
    hgemm_body<EPI>(A, Wt, bias, resid, C, K, N);
}

__global__ void __launch_bounds__(128, 2)
hgemm_qkv(const __half* __restrict__ A,
          const __half* __restrict__ wq, const __half* __restrict__ wk, const __half* __restrict__ wv,
          const float* __restrict__ bq, const float* __restrict__ bk, const float* __restrict__ bv,
          __half* __restrict__ qo, __half* __restrict__ ko, __half* __restrict__ vo,
          int K, int N)
{
    const __half* W  = (blockIdx.z == 0) ? wq : (blockIdx.z == 1) ? wk : wv;
    const float*  bi = (blockIdx.z == 0) ? bq : (blockIdx.z == 1) ? bk : bv;
    __half*       C  = (blockIdx.z == 0) ? qo : (blockIdx.z == 1) ? ko : vo;
    hgemm_body<0>(A, W, bi, nullptr, C, K, N);
}

// ---------------- fp16 causal flash attention: 5-stage KV ring, distance 3 --
#define AST 18432                       // bytes/stage: K 64x72 + V 64x72 halfs
#define ASTAGES 5
#define ATTN_SMEM (ASTAGES*AST)         // 92,160 B

__global__ void __launch_bounds__(256)
attn_tc_kernel(const __half* __restrict__ q, const __half* __restrict__ k,
               const __half* __restrict__ v, __half* __restrict__ o)
{
    extern __shared__ __align__(16) char dsm[];
    const uint32_t smem_base = (uint32_t)__cvta_generic_to_shared(dsm);

    const int bh   = blockIdx.x;
    const int b    = bh / HH;
    const int h    = bh % HH;
    const int T    = (gridDim.y - 1) - blockIdx.y;
    const int q0   = T * 128;
    const int tid  = threadIdx.x;
    const int wid  = tid >> 5;
    const int lane = tid & 31;
    const int lr   = lane >> 2;
    const int lc   = lane & 3;
    const size_t headOff = (size_t)h * DKK;
    const size_t bBase   = (size_t)b * SS;

    // ---- stage Q into stage-0 region, extract register frags ----
    {
        __half* Qst = (__half*)dsm;
        #pragma unroll
        for (int i = 0; i < 4; i++) {
            int c = tid + i * 256;
            int r = c >> 3, ko = (c & 7) * 8;
            *(uint4*)&Qst[r * 72 + ko] = *(const uint4*)(q + (bBase + q0 + r) * DD + headOff + ko);
        }
    }
    __syncthreads();

    const __half2 qscale = __half2half2(__float2half(0.125f));
    uint32_t qf[4][4];
    const int qrow = wid * 16;
    {
        const __half* Qst = (const __half*)dsm;
        #pragma unroll
        for (int kc = 0; kc < 4; kc++) {
            const int kk = kc * 16;
            __half2 t0 = *(__half2*)&Qst[(qrow + lr    ) * 72 + kk + lc * 2];
            __half2 t1 = *(__half2*)&Qst[(qrow + 8 + lr) * 72 + kk + lc * 2];
            __half2 t2 = *(__half2*)&Qst[(qrow + lr    ) * 72 + kk + 8 + lc * 2];
            __half2 t3 = *(__half2*)&Qst[(qrow + 8 + lr) * 72 + kk + 8 + lc * 2];
            t0 = __hmul2(t0, qscale); t1 = __hmul2(t1, qscale);
            t2 = __hmul2(t2, qscale); t3 = __hmul2(t3, qscale);
            qf[kc][0] = *(uint32_t*)&t0; qf[kc][1] = *(uint32_t*)&t1;
            qf[kc][2] = *(uint32_t*)&t2; qf[kc][3] = *(uint32_t*)&t3;
        }
    }
    __syncthreads();   // Q reads done before KV overwrites stage 0

    auto loadKV = [&](int st, int j0) {
        char* base = dsm + st * AST;
        #pragma unroll
        for (int i = 0; i < 2; i++) {
            int c = tid + i * 256;
            int r = c >> 3, ko = (c & 7) * 8;
            cp_async16(base        + (r * 72 + ko) * 2, k + (bBase + j0 + r) * DD + headOff + ko);
            cp_async16(base + 9216 + (r * 72 + ko) * 2, v + (bBase + j0 + r) * DD + headOff + ko);
        }
    };

    const int gq = lane >> 3, rr = lane & 7;
    const uint32_t vlane = ((uint32_t)(((gq & 1) * 8 + rr) * 72 + (gq >> 1) * 8)) * 2;
    const uint32_t klane = ((uint32_t)(((gq >> 1) * 8 + rr) * 72 + (gq & 1) * 8)) * 2;

    float oacc[8][4];
    #pragma unroll
    for (int nv = 0; nv < 8; nv++)
        #pragma unroll
        for (int t = 0; t < 4; t++) oacc[nv][t] = 0.f;
    float m0 = -1e30f, m1 = -1e30f, l0 = 0.f, l1 = 0.f;

    const int qglob0 = q0 + qrow;
    const int nkt = 2 * T + 2;

    // prologue: up to 3 stages
    #pragma unroll
    for (int p = 0; p < 3; p++) {
        if (p < nkt) { loadKV(p, p * 64); CP_COMMIT(); }
    }

    int st = 0, pst = 3;
    for (int kt = 0; kt < nkt; kt++) {
        const int rem = nkt - 1 - kt;
        if (kt + 3 < nkt) {
            loadKV(pst, (kt + 3) * 64);
            CP_COMMIT();
            if (++pst == ASTAGES) pst = 0;
            CP_WAIT(3);
        } else if (rem >= 2) {
            CP_WAIT(2);
        } else if (rem == 1) {
            CP_WAIT(1);
        } else {
            CP_WAIT(0);
        }
        __syncthreads();

        const int j0 = kt * 64;
        if (j0 <= qglob0 + 15) {
            const uint32_t kb = smem_base + st * AST + klane;
            const uint32_t vb = smem_base + st * AST + 9216 + vlane;

            float sacc[8][4];
            #pragma unroll
            for (int nt = 0; nt < 8; nt++)
                sacc[nt][0] = sacc[nt][1] = sacc[nt][2] = sacc[nt][3] = 0.f;
            #pragma unroll
            for (int kc = 0; kc < 4; kc++) {
                #pragma unroll
                for (int np = 0; np < 4; np++) {
                    uint32_t b0, b1, b2, b3;
                    ldsm_x4(b0, b1, b2, b3, kb + np * 2304 + kc * 32);
                    mma_f16(sacc[2*np    ], qf[kc], b0, b1);
                    mma_f16(sacc[2*np + 1], qf[kc], b2, b3);
                }
            }

            if (j0 + 63 > qglob0) {
                const int qi0 = qglob0 + lr, qi1 = qi0 + 8;
                #pragma unroll
                for (int nt = 0; nt < 8; nt++) {
                    const int kj = j0 + nt * 8 + lc * 2;
                    if (kj     > qi0) sacc[nt][0] = -1e30f;
                    if (kj + 1 > qi0) sacc[nt][1] = -1e30f;
                    if (kj     > qi1) sacc[nt][2] = -1e30f;
                    if (kj + 1 > qi1) sacc[nt][3] = -1e30f;
                }
            }

            float mx0 = -1e30f, mx1 = -1e30f;
            #pragma unroll
            for (int nt = 0; nt < 8; nt++) {
                mx0 = fmaxf(mx0, fmaxf(sacc[nt][0], sacc[nt][1]));
                mx1 = fmaxf(mx1, fmaxf(sacc[nt][2], sacc[nt][3]));
            }
            mx0 = fmaxf(mx0, __shfl_xor_sync(0xffffffffu, mx0, 1));
            mx0 = fmaxf(mx0, __shfl_xor_sync(0xffffffffu, mx0, 2));
            mx1 = fmaxf(mx1, __shfl_xor_sync(0xffffffffu, mx1, 1));
            mx1 = fmaxf(mx1, __shfl_xor_sync(0xffffffffu, mx1, 2));

            const float mn0 = fmaxf(m0, mx0);
            const float mn1 = fmaxf(m1, mx1);
            const float sc0 = __expf(m0 - mn0);
            const float sc1 = __expf(m1 - mn1);
            m0 = mn0; m1 = mn1;

            float la0 = 0.f, la1 = 0.f;
            #pragma unroll
            for (int nt = 0; nt < 8; nt++) {
                sacc[nt][0] = __expf(sacc[nt][0] - mn0);
                sacc[nt][1] = __expf(sacc[nt][1] - mn0);
                sacc[nt][2] = __expf(sacc[nt][2] - mn1);
                sacc[nt][3] = __expf(sacc[nt][3] - mn1);
                la0 += sacc[nt][0] + sacc[nt][1];
                la1 += sacc[nt][2] + sacc[nt][3];
            }

            #pragma unroll
            for (int nv = 0; nv < 8; nv++) {
                oacc[nv][0] *= sc0; oacc[nv][1] *= sc0;
                oacc[nv][2] *= sc1; oacc[nv][3] *= sc1;
            }

            uint32_t pf[4][4];
            #pragma unroll
            for (int pk = 0; pk < 4; pk++) {
                __half2 h0 = __floats2half2_rn(sacc[2*pk    ][0], sacc[2*pk    ][1]);
                __half2 h1 = __floats2half2_rn(sacc[2*pk    ][2], sacc[2*pk    ][3]);
                __half2 h2 = __floats2half2_rn(sacc[2*pk + 1][0], sacc[2*pk + 1][1]);
                __half2 h3 = __floats2half2_rn(sacc[2*pk + 1][2], sacc[2*pk + 1][3]);
                pf[pk][0] = *(uint32_t*)&h0;
                pf[pk][1] = *(uint32_t*)&h1;
                pf[pk][2] = *(uint32_t*)&h2;
                pf[pk][3] = *(uint32_t*)&h3;
            }

            #pragma unroll
            for (int nh = 0; nh < 4; nh++) {
                #pragma unroll
                for (int pk = 0; pk < 4; pk++) {
                    uint32_t b0, b1, b2, b3;
                    ldsm_x4_t(b0, b1, b2, b3, vb + pk * 2304 + nh * 32);
                    mma_f16(oacc[2*nh    ], pf[pk], b0, b1);
                    mma_f16(oacc[2*nh + 1], pf[pk], b2, b3);
                }
            }

            la0 += __shfl_xor_sync(0xffffffffu, la0, 1);
            la0 += __shfl_xor_sync(0xffffffffu, la0, 2);
            la1 += __shfl_xor_sync(0xffffffffu, la1, 1);
            la1 += __shfl_xor_sync(0xffffffffu, la1, 2);
            l0 = l0 * sc0 + la0;
            l1 = l1 * sc1 + la1;
        }
        __syncthreads();          // WAR: stage st becomes prefetch target in 2 iters
        if (++st == ASTAGES) st = 0;
    }

    const float inv0 = 1.f / l0;
    const float inv1 = 1.f / l1;
    const size_t r0 = bBase + q0 + qrow + lr;
    #pragma unroll
    for (int nv = 0; nv < 8; nv++) {
        const int col = nv * 8 + lc * 2;
        *(__half2*)&o[r0 * DD + headOff + col] =
            __floats2half2_rn(oacc[nv][0] * inv0, oacc[nv][1] * inv0);
        *(__half2*)&o[(r0 + 8) * DD + headOff + col] =
            __floats2half2_rn(oacc[nv][2] * inv1, oacc[nv][3] * inv1);
    }
}

// ---------------- host launcher ----------------
extern "C" void kernel_launch(void* const* d_in, const int* in_sizes, int n_in,
                              void* d_out, int out_size)
{
    const float* x    = (const float*)d_in[0];
    const float* ln1g = (const float*)d_in[1];
    const float* ln1b = (const float*)d_in[2];
    const float* wq   = (const float*)d_in[3];
    const float* bq   = (const float*)d_in[4];
    const float* wk   = (const float*)d_in[5];
    const float* bk   = (const float*)d_in[6];
    const float* wv   = (const float*)d_in[7];
    const float* bv   = (const float*)d_in[8];
    const float* wo   = (const float*)d_in[9];
    const float* bo   = (const float*)d_in[10];
    const float* ln2g = (const float*)d_in[11];
    const float* ln2b = (const float*)d_in[12];
    const float* w1   = (const float*)d_in[13];
    const float* b1   = (const float*)d_in[14];
    const float* w2   = (const float*)d_in[15];
    const float* b2   = (const float*)d_in[16];
    float* out = (float*)d_out;

    __half *ln1, *qb, *kb, *vb, *attn, *ln2, *ffn1;
    __half *twq, *twk, *twv, *two, *tw1, *tw2;
    float *x1;
    cudaGetSymbolAddress((void**)&ln1,  h_ln1);
    cudaGetSymbolAddress((void**)&qb,   h_q);
    cudaGetSymbolAddress((void**)&kb,   h_k);
    cudaGetSymbolAddress((void**)&vb,   h_v);
    cudaGetSymbolAddress((void**)&attn, h_attn);
    cudaGetSymbolAddress((void**)&x1,   g_x1);
    cudaGetSymbolAddress((void**)&ln2,  h_ln2);
    cudaGetSymbolAddress((void**)&ffn1, h_ffn1);
    cudaGetSymbolAddress((void**)&twq,  h_wq);
    cudaGetSymbolAddress((void**)&twk,  h_wk);
    cudaGetSymbolAddress((void**)&twv,  h_wv);
    cudaGetSymbolAddress((void**)&two,  h_wo);
    cudaGetSymbolAddress((void**)&tw1,  h_w1);
    cudaGetSymbolAddress((void**)&tw2,  h_w2);

    cudaFuncSetAttribute(hgemm<0>,  cudaFuncAttributeMaxDynamicSharedMemorySize, GSMEM);
    cudaFuncSetAttribute(hgemm<1>,  cudaFuncAttributeMaxDynamicSharedMemorySize, GSMEM);
    cudaFuncSetAttribute(hgemm<2>,  cudaFuncAttributeMaxDynamicSharedMemorySize, GSMEM);
    cudaFuncSetAttribute(hgemm_qkv, cudaFuncAttributeMaxDynamicSharedMemorySize, GSMEM);
    cudaFuncSetAttribute(attn_tc_kernel, cudaFuncAttributeMaxDynamicSharedMemorySize, ATTN_SMEM);

    // 0) fused: weight converts + LN1 in one launch
    prep_kernel<<<6912 + MROWS, 256>>>(wq, wk, wv, wo, w1, w2,
                                       twq, twk, twv, two, tw1, tw2,
                                       x, ln1g, ln1b, ln1);

    // 1) QKV projections (1152 CTAs)
    hgemm_qkv<<<dim3(DD / 64, MROWS / 128, 3), 128, GSMEM>>>(
        ln1, twq, twk, twv, bq, bk, bv, qb, kb, vb, DD, DD);

    // 2) causal attention (5-stage KV ring)
    attn_tc_kernel<<<dim3(BB * HH, SS / 128), 256, ATTN_SMEM>>>(qb, kb, vb, attn);

    // 3) O projection + residual -> f32 x1 (384 CTAs)
    hgemm<1><<<dim3(DD / 64, MROWS / 128), 128, GSMEM>>>(attn, two, bo, x, x1, DD, DD);

    // 4) LN2 -> half
    ln_kernel<<<MROWS, 256>>>(x1, ln2g, ln2b, ln2);

    // 5) FFN up + GELU -> half (1536 CTAs)
    hgemm<2><<<dim3(DFF / 64, MROWS / 128), 128, GSMEM>>>(ln2, tw1, b1, nullptr, ffn1, DD, DFF);

    // 6) FFN down + residual -> f32 out (384 CTAs)
    hgemm<1><<<dim3(DD / 64, MROWS / 128), 128, GSMEM>>>(ffn1, tw2, b2, x1, out, DFF, DD);
}

// round 13
// speedup vs baseline: 1.1148x; 1.1148x over previous
#include <cuda_runtime.h>
#include <cuda_fp16.h>
#include <math.h>
#include <stdint.h>

#define BB 2
#define SS 2048
#define DD 768
#define HH 12
#define DKK 64
#define DFF 3072
#define MROWS (BB*SS)   // 4096

// ---------------- scratch (device globals: allocation-free) ----------------
__device__ __half h_ln1 [MROWS*DD];
__device__ __half h_q   [MROWS*DD];
__device__ __half h_k   [MROWS*DD];
__device__ __half h_v   [MROWS*DD];
__device__ __half h_attn[MROWS*DD];
__device__ float  g_x1  [MROWS*DD];
__device__ __half h_ln2 [MROWS*DD];
__device__ __half h_ffn1[MROWS*DFF];
// transposed half weights: Wt[N][K]
__device__ __half h_wq[DD*DD];
__device__ __half h_wk[DD*DD];
__device__ __half h_wv[DD*DD];
__device__ __half h_wo[DD*DD];
__device__ __half h_w1[DD*DFF];
__device__ __half h_w2[DFF*DD];

// ---------------- helpers ----------------
__device__ __forceinline__ float gelu_exact(float v) {
    return 0.5f * v * (1.0f + erff(v * 0.70710678118654752f));
}
__device__ __forceinline__ void cp_async16(void* smem, const void* gmem) {
    uint32_t s = (uint32_t)__cvta_generic_to_shared(smem);
    asm volatile("cp.async.cg.shared.global [%0], [%1], 16;\n" :: "r"(s), "l"(gmem));
}
#define CP_COMMIT() asm volatile("cp.async.commit_group;\n" ::)
#define CP_WAIT(n)  asm volatile("cp.async.wait_group %0;\n" :: "n"(n))

__device__ __forceinline__ void mma_f16(float* c, const uint32_t* a, uint32_t b0, uint32_t b1) {
    asm volatile(
      "mma.sync.aligned.m16n8k16.row.col.f32.f16.f16.f32 "
      "{%0,%1,%2,%3}, {%4,%5,%6,%7}, {%8,%9}, {%0,%1,%2,%3};\n"
      : "+f"(c[0]), "+f"(c[1]), "+f"(c[2]), "+f"(c[3])
      : "r"(a[0]), "r"(a[1]), "r"(a[2]), "r"(a[3]), "r"(b0), "r"(b1));
}
__device__ __forceinline__ void ldsm_x4(uint32_t& r0, uint32_t& r1, uint32_t& r2, uint32_t& r3,
                                        uint32_t addr) {
    asm volatile("ldmatrix.sync.aligned.m8n8.x4.shared.b16 {%0,%1,%2,%3}, [%4];\n"
      : "=r"(r0), "=r"(r1), "=r"(r2), "=r"(r3) : "r"(addr));
}
__device__ __forceinline__ void ldsm_x4_t(uint32_t& r0, uint32_t& r1, uint32_t& r2, uint32_t& r3,
                                          uint32_t addr) {
    asm volatile("ldmatrix.sync.aligned.m8n8.x4.trans.shared.b16 {%0,%1,%2,%3}, [%4];\n"
      : "=r"(r0), "=r"(r1), "=r"(r2), "=r"(r3) : "r"(addr));
}

// ---------------- fused prep: 6 weight transposes + LN1, one launch --------
__global__ void __launch_bounds__(256)
prep_kernel(const float* __restrict__ wq, const float* __restrict__ wk,
            const float* __restrict__ wv, const float* __restrict__ wo,
            const float* __restrict__ w1, const float* __restrict__ w2,
            __half* __restrict__ twq, __half* __restrict__ twk,
            __half* __restrict__ twv, __half* __restrict__ two,
            __half* __restrict__ tw1, __half* __restrict__ tw2,
            const float* __restrict__ x, const float* __restrict__ gamma,
            const float* __restrict__ beta, __half* __restrict__ lnout)
{
    __shared__ float sb[32*33];
    const int idx = blockIdx.x;
    const int tid = threadIdx.x;

    if (idx < 6912) {
        const float* W; __half* Wt; int K, N, tk, tn;
        if (idx < 2304) {
            const int which = idx / 576, r = idx % 576;
            W  = (which == 0) ? wq  : (which == 1) ? wk  : (which == 2) ? wv  : wo;
            Wt = (which == 0) ? twq : (which == 1) ? twk : (which == 2) ? twv : two;
            K = DD; N = DD; tk = r % 24; tn = r / 24;
        } else if (idx < 4608) {
            const int r = idx - 2304;
            W = w1; Wt = tw1; K = DD; N = DFF; tk = r % 24; tn = r / 24;
        } else {
            const int r = idx - 4608;
            W = w2; Wt = tw2; K = DFF; N = DD; tk = r % 96; tn = r / 96;
        }
        const int k0 = tk * 32, n0 = tn * 32;
        const int tx = tid & 31, ty = tid >> 5;       // 32 x 8
        #pragma unroll
        for (int i = 0; i < 32; i += 8)
            sb[(ty + i) * 33 + tx] = W[(size_t)(k0 + ty + i) * N + n0 + tx];
        __syncthreads();
        #pragma unroll
        for (int i = 0; i < 32; i += 8)
            Wt[(size_t)(n0 + ty + i) * K + k0 + tx] = __float2half_rn(sb[tx * 33 + ty + i]);
    } else {
        const int row = idx - 6912;
        const float* xr = x + (size_t)row * DD;
        float a = xr[tid], b = xr[tid + 256], c = xr[tid + 512];
        float s  = a + b + c;
        float ss = a*a + b*b + c*c;
        #pragma unroll
        for (int off = 16; off > 0; off >>= 1) {
            s  += __shfl_xor_sync(0xffffffffu, s,  off);
            ss += __shfl_xor_sync(0xffffffffu, ss, off);
        }
        int wid = tid >> 5, lane = tid & 31;
        if (lane == 0) { sb[wid] = s; sb[8 + wid] = ss; }
        __syncthreads();
        float tot = 0.f, tot2 = 0.f;
        #pragma unroll
        for (int i = 0; i < 8; i++) { tot += sb[i]; tot2 += sb[8 + i]; }
        float mean = tot * (1.0f / DD);
        float var  = tot2 * (1.0f / DD) - mean * mean;
        float rstd = rsqrtf(var + 1e-7f);
        __half* orow = lnout + (size_t)row * DD;
        orow[tid      ] = __float2half_rn(gamma[tid      ] * (a - mean) * rstd + beta[tid      ]);
        orow[tid + 256] = __float2half_rn(gamma[tid + 256] * (b - mean) * rstd + beta[tid + 256]);
        orow[tid + 512] = __float2half_rn(gamma[tid + 512] * (c - mean) * rstd + beta[tid + 512]);
    }
}

// ---------------- LayerNorm (standalone, for LN2) ----------------
__global__ void ln_kernel(const float* __restrict__ x,
                          const float* __restrict__ gamma,
                          const float* __restrict__ beta,
                          __half* __restrict__ out)
{
    int row = blockIdx.x;
    const float* xr = x + (size_t)row * DD;
    int tid = threadIdx.x;

    float a = xr[tid], b = xr[tid + 256], c = xr[tid + 512];
    float s  = a + b + c;
    float ss = a*a + b*b + c*c;
    #pragma unroll
    for (int off = 16; off > 0; off >>= 1) {
        s  += __shfl_xor_sync(0xffffffffu, s,  off);
        ss += __shfl_xor_sync(0xffffffffu, ss, off);
    }
    __shared__ float sh0[8], sh1[8];
    int wid = tid >> 5, lane = tid & 31;
    if (lane == 0) { sh0[wid] = s; sh1[wid] = ss; }
    __syncthreads();
    float tot = 0.f, tot2 = 0.f;
    #pragma unroll
    for (int i = 0; i < 8; i++) { tot += sh0[i]; tot2 += sh1[i]; }
    float mean = tot * (1.0f / DD);
    float var  = tot2 * (1.0f / DD) - mean * mean;
    float rstd = rsqrtf(var + 1e-7f);

    __half* orow = out + (size_t)row * DD;
    orow[tid      ] = __float2half_rn(gamma[tid      ] * (a - mean) * rstd + beta[tid      ]);
    orow[tid + 256] = __float2half_rn(gamma[tid + 256] * (b - mean) * rstd + beta[tid + 256]);
    orow[tid + 512] = __float2half_rn(gamma[tid + 512] * (c - mean) * rstd + beta[tid + 512]);
}

// ---------------- fp16 tensor-core GEMM: templated BN, 4-stage ring -------
// C[M,N] = A[M,K](f16) @ Wt[N,K](f16)^T + bias(f32)
// CTA 128xBN, BK=32, 4 warps (2 x 2), warp tile 64 x (BN/2), one sync/iter.
// EPI: 0 = bias -> half | 1 = bias + resid -> f32 | 2 = bias + GELU -> half
template<int EPI, int BN>
__device__ __forceinline__ void hgemm_body(
    const __half* __restrict__ A, const __half* __restrict__ Wt,
    const float* __restrict__ bias, const float* __restrict__ resid,
    void* __restrict__ Cv, int K, int N)
{
    constexpr int WN   = BN / 2;         // per-warp n extent (64 or 32)
    constexpr int NJ   = WN / 8;         // n8 tiles per warp (8 or 4)
    constexpr int JP   = WN / 16;        // ldsm x4 pairs (4 or 2)
    constexpr int STG  = 10240 + BN * 80;   // As 128x40x2 + Bs BNx40x2 bytes

    extern __shared__ __align__(16) char dsm[];

    const int tid  = threadIdx.x;
    const int wid  = tid >> 5;
    const int lane = tid & 31;
    const int lr   = lane >> 2;
    const int lc   = lane & 3;
    const int wm   = wid >> 1;        // 0..1
    const int wn   = wid & 1;         // 0..1

    const int rowBase = blockIdx.y * 128;
    const int colBase = blockIdx.x * BN;

    float acc[4][NJ][4];
    #pragma unroll
    for (int i = 0; i < 4; i++)
        #pragma unroll
        for (int j = 0; j < NJ; j++)
            #pragma unroll
            for (int q = 0; q < 4; q++) acc[i][j][q] = 0.f;

    auto load_tiles = [&](int st, int k0) {
        __half (*As)[40] = (__half(*)[40])(dsm + st * STG);
        __half (*Bs)[40] = (__half(*)[40])(dsm + st * STG + 10240);
        #pragma unroll
        for (int i = 0; i < 4; i++) {
            int c = tid + i * 128;          // A: 128 rows x 4 chunks
            int r = c >> 2, ko = (c & 3) * 8;
            cp_async16(&As[r][ko], A + (size_t)(rowBase + r) * K + k0 + ko);
        }
        #pragma unroll
        for (int i = 0; i < BN / 32; i++) {
            int c = tid + i * 128;          // B: BN rows x 4 chunks
            int r = c >> 2, ko = (c & 3) * 8;
            cp_async16(&Bs[r][ko], Wt + (size_t)(colBase + r) * K + k0 + ko);
        }
    };

    const int g = lane >> 3;
    const int grow = lane & 7;
    const int aRowOff = ((g & 1) * 8 + grow);
    const int aColOff = (g >> 1) * 8;
    const int bRowOff = ((g >> 1) * 8 + grow);
    const int bColOff = (g & 1) * 8;

    const int niter = K >> 5;
    load_tiles(0, 0);  CP_COMMIT();
    load_tiles(1, 32); CP_COMMIT();

    for (int it = 0; it < niter; it++) {
        const int st  = it & 3;
        const int pre = it + 2;
        if (pre < niter) {
            load_tiles(pre & 3, pre << 5);
            CP_COMMIT();
            CP_WAIT(2);
        } else if (it + 1 < niter) {
            CP_WAIT(1);
        } else {
            CP_WAIT(0);
        }
        __syncthreads();

        __half (*As)[40] = (__half(*)[40])(dsm + st * STG);
        __half (*Bs)[40] = (__half(*)[40])(dsm + st * STG + 10240);
        #pragma unroll
        for (int kc = 0; kc < 2; kc++) {
            const int kk = kc * 16;
            uint32_t bf[NJ][2];
            #pragma unroll
            for (int jp = 0; jp < JP; jp++) {
                const int n = wn * WN + jp * 16 + bRowOff;
                uint32_t addr = (uint32_t)__cvta_generic_to_shared(&Bs[n][kk + bColOff]);
                ldsm_x4(bf[2*jp][0], bf[2*jp][1], bf[2*jp+1][0], bf[2*jp+1][1], addr);
            }
            #pragma unroll
            for (int i = 0; i < 4; i++) {
                const int m = wm * 64 + i * 16;
                uint32_t a[4];
                uint32_t addr = (uint32_t)__cvta_generic_to_shared(&As[m + aRowOff][kk + aColOff]);
                ldsm_x4(a[0], a[1], a[2], a[3], addr);
                #pragma unroll
                for (int j = 0; j < NJ; j++) mma_f16(acc[i][j], a, bf[j][0], bf[j][1]);
            }
        }
    }

    const int row0 = rowBase + wm * 64;
    const int col0 = colBase + wn * WN;
    __half* Ch = (__half*)Cv;
    float*  Cf = (float*)Cv;
    #pragma unroll
    for (int j = 0; j < NJ; j++) {
        const int col = col0 + j * 8 + lc * 2;
        const float b0v = bias[col], b1v = bias[col + 1];
        #pragma unroll
        for (int i = 0; i < 4; i++) {
            const int r0 = row0 + i * 16 + lr;
            float v0 = acc[i][j][0] + b0v;
            float v1 = acc[i][j][1] + b1v;
            float v2 = acc[i][j][2] + b0v;
            float v3 = acc[i][j][3] + b1v;
            if (EPI == 1) {
                v0 += resid[(size_t)r0 * N + col];
                v1 += resid[(size_t)r0 * N + col + 1];
                v2 += resid[(size_t)(r0 + 8) * N + col];
                v3 += resid[(size_t)(r0 + 8) * N + col + 1];
                *(float2*)&Cf[(size_t)r0 * N + col]       = make_float2(v0, v1);
                *(float2*)&Cf[(size_t)(r0 + 8) * N + col] = make_float2(v2, v3);
            } else {
                if (EPI == 2) {
                    v0 = gelu_exact(v0); v1 = gelu_exact(v1);
                    v2 = gelu_exact(v2); v3 = gelu_exact(v3);
                }
                *(__half2*)&Ch[(size_t)r0 * N + col]       = __floats2half2_rn(v0, v1);
                *(__half2*)&Ch[(size_t)(r0 + 8) * N + col] = __floats2half2_rn(v2, v3);
            }
        }
    }
}

#define GSMEM_W (4*(10240+128*80))   // 81,920 B (BN=128)
#define GSMEM_N (4*(10240+64*80))    // 61,440 B (BN=64)

template<int EPI>
__global__ void __launch_bounds__(128, 2)
hgemmW(const __half* __restrict__ A, const __half* __restrict__ Wt,
       const float* __restrict__ bias, const float* __restrict__ resid,
       void* __restrict__ C, int K, int N)
{
    hgemm_body<EPI, 128>(A, Wt, bias, resid, C, K, N);
}

template<int EPI>
__global__ void __launch_bounds__(128, 3)
hgemmN(const __half* __restrict__ A, const __half* __restrict__ Wt,
       const float* __restrict__ bias, const float* __restrict__ resid,
       void* __restrict__ C, int K, int N)
{
    hgemm_body<EPI, 64>(A, Wt, bias, resid, C, K, N);
}

__global__ void __launch_bounds__(128, 2)
hgemm_qkv(const __half* __restrict__ A,
          const __half* __restrict__ wq, const __half* __restrict__ wk, const __half* __restrict__ wv,
          const float* __restrict__ bq, const float* __restrict__ bk, const float* __restrict__ bv,
          __half* __restrict__ qo, __half* __restrict__ ko, __half* __restrict__ vo,
          int K, int N)
{
    const __half* W  = (blockIdx.z == 0) ? wq : (blockIdx.z == 1) ? wk : wv;
    const float*  bi = (blockIdx.z == 0) ? bq : (blockIdx.z == 1) ? bk : bv;
    __half*       C  = (blockIdx.z == 0) ? qo : (blockIdx.z == 1) ? ko : vo;
    hgemm_body<0, 128>(A, W, bi, nullptr, C, K, N);
}

// ---------------- fp16 causal flash attention: 4-stage KV ring, exp2 -------
// grid (B*H, S/128), 256 threads (8 warps); warp owns 16 query rows.
// Scores carried in log2 domain: Q pre-scaled by log2(e)/sqrt(dk).
#define AST 18432
#define ATTN_SMEM (4*AST)               // 73,728 B

__global__ void __launch_bounds__(256)
attn_tc_kernel(const __half* __restrict__ q, const __half* __restrict__ k,
               const __half* __restrict__ v, __half* __restrict__ o)
{
    extern __shared__ __align__(16) char dsm[];
    const uint32_t smem_base = (uint32_t)__cvta_generic_to_shared(dsm);

    const int bh   = blockIdx.x;
    const int b    = bh / HH;
    const int h    = bh % HH;
    const int T    = (gridDim.y - 1) - blockIdx.y;
    const int q0   = T * 128;
    const int tid  = threadIdx.x;
    const int wid  = tid >> 5;
    const int lane = tid & 31;
    const int lr   = lane >> 2;
    const int lc   = lane & 3;
    const size_t headOff = (size_t)h * DKK;
    const size_t bBase   = (size_t)b * SS;

    {
        __half* Qst = (__half*)dsm;
        #pragma unroll
        for (int i = 0; i < 4; i++) {
            int c = tid + i * 256;
            int r = c >> 3, ko = (c & 7) * 8;
            *(uint4*)&Qst[r * 72 + ko] = *(const uint4*)(q + (bBase + q0 + r) * DD + headOff + ko);
        }
    }
    __syncthreads();

    // scale = log2(e)/sqrt(64): scores land in log2 domain
    const __half2 qscale = __half2half2(__float2half(0.18033688f));
    uint32_t qf[4][4];
    const int qrow = wid * 16;
    {
        const __half* Qst = (const __half*)dsm;
        #pragma unroll
        for (int kc = 0; kc < 4; kc++) {
            const int kk = kc * 16;
            __half2 t0 = *(__half2*)&Qst[(qrow + lr    ) * 72 + kk + lc * 2];
            __half2 t1 = *(__half2*)&Qst[(qrow + 8 + lr) * 72 + kk + lc * 2];
            __half2 t2 = *(__half2*)&Qst[(qrow + lr    ) * 72 + kk + 8 + lc * 2];
            __half2 t3 = *(__half2*)&Qst[(qrow + 8 + lr) * 72 + kk + 8 + lc * 2];
            t0 = __hmul2(t0, qscale); t1 = __hmul2(t1, qscale);
            t2 = __hmul2(t2, qscale); t3 = __hmul2(t3, qscale);
            qf[kc][0] = *(uint32_t*)&t0; qf[kc][1] = *(uint32_t*)&t1;
            qf[kc][2] = *(uint32_t*)&t2; qf[kc][3] = *(uint32_t*)&t3;
        }
    }
    __syncthreads();

    auto loadKV = [&](int st, int j0) {
        char* base = dsm + st * AST;
        #pragma unroll
        for (int i = 0; i < 2; i++) {
            int c = tid + i * 256;
            int r = c >> 3, ko = (c & 7) * 8;
            cp_async16(base        + (r * 72 + ko) * 2, k + (bBase + j0 + r) * DD + headOff + ko);
            cp_async16(base + 9216 + (r * 72 + ko) * 2, v + (bBase + j0 + r) * DD + headOff + ko);
        }
    };

    const int gq = lane >> 3, rr = lane & 7;
    const uint32_t vlane = ((uint32_t)(((gq & 1) * 8 + rr) * 72 + (gq >> 1) * 8)) * 2;
    const uint32_t klane = ((uint32_t)(((gq >> 1) * 8 + rr) * 72 + (gq & 1) * 8)) * 2;

    float oacc[8][4];
    #pragma unroll
    for (int nv = 0; nv < 8; nv++)
        #pragma unroll
        for (int t = 0; t < 4; t++) oacc[nv][t] = 0.f;
    float m0 = -1e30f, m1 = -1e30f, l0 = 0.f, l1 = 0.f;

    const int qglob0 = q0 + qrow;
    const int nkt = 2 * T + 2;

    loadKV(0, 0);  CP_COMMIT();
    loadKV(1, 64); CP_COMMIT();

    for (int kt = 0; kt < nkt; kt++) {
        const int st = kt & 3;
        const int j0 = kt * 64;
        if (kt + 2 < nkt) {
            loadKV((kt + 2) & 3, (kt + 2) * 64);
            CP_COMMIT();
            CP_WAIT(2);
        } else if (kt + 1 < nkt) {
            CP_WAIT(1);
        } else {
            CP_WAIT(0);
        }
        __syncthreads();

        if (j0 <= qglob0 + 15) {
            const uint32_t kb = smem_base + st * AST + klane;
            const uint32_t vb = smem_base + st * AST + 9216 + vlane;

            float sacc[8][4];
            #pragma unroll
            for (int nt = 0; nt < 8; nt++)
                sacc[nt][0] = sacc[nt][1] = sacc[nt][2] = sacc[nt][3] = 0.f;
            #pragma unroll
            for (int kc = 0; kc < 4; kc++) {
                #pragma unroll
                for (int np = 0; np < 4; np++) {
                    uint32_t b0, b1, b2, b3;
                    ldsm_x4(b0, b1, b2, b3, kb + np * 2304 + kc * 32);
                    mma_f16(sacc[2*np    ], qf[kc], b0, b1);
                    mma_f16(sacc[2*np + 1], qf[kc], b2, b3);
                }
            }

            if (j0 + 63 > qglob0) {
                const int qi0 = qglob0 + lr, qi1 = qi0 + 8;
                #pragma unroll
                for (int nt = 0; nt < 8; nt++) {
                    const int kj = j0 + nt * 8 + lc * 2;
                    if (kj     > qi0) sacc[nt][0] = -1e30f;
                    if (kj + 1 > qi0) sacc[nt][1] = -1e30f;
                    if (kj     > qi1) sacc[nt][2] = -1e30f;
                    if (kj + 1 > qi1) sacc[nt][3] = -1e30f;
                }
            }

            float mx0 = -1e30f, mx1 = -1e30f;
            #pragma unroll
            for (int nt = 0; nt < 8; nt++) {
                mx0 = fmaxf(mx0, fmaxf(sacc[nt][0], sacc[nt][1]));
                mx1 = fmaxf(mx1, fmaxf(sacc[nt][2], sacc[nt][3]));
            }
            mx0 = fmaxf(mx0, __shfl_xor_sync(0xffffffffu, mx0, 1));
            mx0 = fmaxf(mx0, __shfl_xor_sync(0xffffffffu, mx0, 2));
            mx1 = fmaxf(mx1, __shfl_xor_sync(0xffffffffu, mx1, 1));
            mx1 = fmaxf(mx1, __shfl_xor_sync(0xffffffffu, mx1, 2));

            const float mn0 = fmaxf(m0, mx0);
            const float mn1 = fmaxf(m1, mx1);
            const float sc0 = exp2f(m0 - mn0);
            const float sc1 = exp2f(m1 - mn1);
            m0 = mn0; m1 = mn1;

            float la0 = 0.f, la1 = 0.f;
            #pragma unroll
            for (int nt = 0; nt < 8; nt++) {
                sacc[nt][0] = exp2f(sacc[nt][0] - mn0);
                sacc[nt][1] = exp2f(sacc[nt][1] - mn0);
                sacc[nt][2] = exp2f(sacc[nt][2] - mn1);
                sacc[nt][3] = exp2f(sacc[nt][3] - mn1);
                la0 += sacc[nt][0] + sacc[nt][1];
                la1 += sacc[nt][2] + sacc[nt][3];
            }

            #pragma unroll
            for (int nv = 0; nv < 8; nv++) {
                oacc[nv][0] *= sc0; oacc[nv][1] *= sc0;
                oacc[nv][2] *= sc1; oacc[nv][3] *= sc1;
            }

            uint32_t pf[4][4];
            #pragma unroll
            for (int pk = 0; pk < 4; pk++) {
                __half2 h0 = __floats2half2_rn(sacc[2*pk    ][0], sacc[2*pk    ][1]);
                __half2 h1 = __floats2half2_rn(sacc[2*pk    ][2], sacc[2*pk    ][3]);
                __half2 h2 = __floats2half2_rn(sacc[2*pk + 1][0], sacc[2*pk + 1][1]);
                __half2 h3 = __floats2half2_rn(sacc[2*pk + 1][2], sacc[2*pk + 1][3]);
                pf[pk][0] = *(uint32_t*)&h0;
                pf[pk][1] = *(uint32_t*)&h1;
                pf[pk][2] = *(uint32_t*)&h2;
                pf[pk][3] = *(uint32_t*)&h3;
            }

            #pragma unroll
            for (int nh = 0; nh < 4; nh++) {
                #pragma unroll
                for (int pk = 0; pk < 4; pk++) {
                    uint32_t b0, b1, b2, b3;
                    ldsm_x4_t(b0, b1, b2, b3, vb + pk * 2304 + nh * 32);
                    mma_f16(oacc[2*nh    ], pf[pk], b0, b1);
                    mma_f16(oacc[2*nh + 1], pf[pk], b2, b3);
                }
            }

            la0 += __shfl_xor_sync(0xffffffffu, la0, 1);
            la0 += __shfl_xor_sync(0xffffffffu, la0, 2);
            la1 += __shfl_xor_sync(0xffffffffu, la1, 1);
            la1 += __shfl_xor_sync(0xffffffffu, la1, 2);
            l0 = l0 * sc0 + la0;
            l1 = l1 * sc1 + la1;
        }
    }

    const float inv0 = 1.f / l0;
    const float inv1 = 1.f / l1;
    const size_t r0 = bBase + q0 + qrow + lr;
    #pragma unroll
    for (int nv = 0; nv < 8; nv++) {
        const int col = nv * 8 + lc * 2;
        *(__half2*)&o[r0 * DD + headOff + col] =
            __floats2half2_rn(oacc[nv][0] * inv0, oacc[nv][1] * inv0);
        *(__half2*)&o[(r0 + 8) * DD + headOff + col] =
            __floats2half2_rn(oacc[nv][2] * inv1, oacc[nv][3] * inv1);
    }
}

// ---------------- host launcher ----------------
extern "C" void kernel_launch(void* const* d_in, const int* in_sizes, int n_in,
                              void* d_out, int out_size)
{
    const float* x    = (const float*)d_in[0];
    const float* ln1g = (const float*)d_in[1];
    const float* ln1b = (const float*)d_in[2];
    const float* wq   = (const float*)d_in[3];
    const float* bq   = (const float*)d_in[4];
    const float* wk   = (const float*)d_in[5];
    const float* bk   = (const float*)d_in[6];
    const float* wv   = (const float*)d_in[7];
    const float* bv   = (const float*)d_in[8];
    const float* wo   = (const float*)d_in[9];
    const float* bo   = (const float*)d_in[10];
    const float* ln2g = (const float*)d_in[11];
    const float* ln2b = (const float*)d_in[12];
    const float* w1   = (const float*)d_in[13];
    const float* b1   = (const float*)d_in[14];
    const float* w2   = (const float*)d_in[15];
    const float* b2   = (const float*)d_in[16];
    float* out = (float*)d_out;

    __half *ln1, *qb, *kb, *vb, *attn, *ln2, *ffn1;
    __half *twq, *twk, *twv, *two, *tw1, *tw2;
    float *x1;
    cudaGetSymbolAddress((void**)&ln1,  h_ln1);
    cudaGetSymbolAddress((void**)&qb,   h_q);
    cudaGetSymbolAddress((void**)&kb,   h_k);
    cudaGetSymbolAddress((void**)&vb,   h_v);
    cudaGetSymbolAddress((void**)&attn, h_attn);
    cudaGetSymbolAddress((void**)&x1,   g_x1);
    cudaGetSymbolAddress((void**)&ln2,  h_ln2);
    cudaGetSymbolAddress((void**)&ffn1, h_ffn1);
    cudaGetSymbolAddress((void**)&twq,  h_wq);
    cudaGetSymbolAddress((void**)&twk,  h_wk);
    cudaGetSymbolAddress((void**)&twv,  h_wv);
    cudaGetSymbolAddress((void**)&two,  h_wo);
    cudaGetSymbolAddress((void**)&tw1,  h_w1);
    cudaGetSymbolAddress((void**)&tw2,  h_w2);

    cudaFuncSetAttribute(hgemmW<0>, cudaFuncAttributeMaxDynamicSharedMemorySize, GSMEM_W);
    cudaFuncSetAttribute(hgemmW<2>, cudaFuncAttributeMaxDynamicSharedMemorySize, GSMEM_W);
    cudaFuncSetAttribute(hgemmN<1>, cudaFuncAttributeMaxDynamicSharedMemorySize, GSMEM_N);
    cudaFuncSetAttribute(hgemm_qkv, cudaFuncAttributeMaxDynamicSharedMemorySize, GSMEM_W);
    cudaFuncSetAttribute(attn_tc_kernel, cudaFuncAttributeMaxDynamicSharedMemorySize, ATTN_SMEM);

    // 0) fused: weight converts + LN1 in one launch
    prep_kernel<<<6912 + MROWS, 256>>>(wq, wk, wv, wo, w1, w2,
                                       twq, twk, twv, two, tw1, tw2,
                                       x, ln1g, ln1b, ln1);

    // 1) QKV projections (wide tile, 576 CTAs)
    hgemm_qkv<<<dim3(DD / 128, MROWS / 128, 3), 128, GSMEM_W>>>(
        ln1, twq, twk, twv, bq, bk, bv, qb, kb, vb, DD, DD);

    // 2) causal attention
    attn_tc_kernel<<<dim3(BB * HH, SS / 128), 256, ATTN_SMEM>>>(qb, kb, vb, attn);

    // 3) O projection + residual -> f32 x1 (narrow tile, 384 CTAs)
    hgemmN<1><<<dim3(DD / 64, MROWS / 128), 128, GSMEM_N>>>(attn, two, bo, x, x1, DD, DD);

    // 4) LN2 -> half
    ln_kernel<<<MROWS, 256>>>(x1, ln2g, ln2b, ln2);

    // 5) FFN up + GELU -> half (wide tile, 768 CTAs)
    hgemmW<2><<<dim3(DFF / 128, MROWS / 128), 128, GSMEM_W>>>(ln2, tw1, b1, nullptr, ffn1, DD, DFF);

    // 6) FFN down + residual -> f32 out (narrow tile, 384 CTAs)
    hgemmN<1><<<dim3(DD / 64, MROWS / 128), 128, GSMEM_N>>>(ffn1, tw2, b2, x1, out, DFF, DD);
}

// round 14
// speedup vs baseline: 1.1249x; 1.0090x over previous
#include <cuda_runtime.h>
#include <cuda_fp16.h>
#include <math.h>
#include <stdint.h>

#define BB 2
#define SS 2048
#define DD 768
#define HH 12
#define DKK 64
#define DFF 3072
#define MROWS (BB*SS)   // 4096

// ---------------- scratch (device globals: allocation-free) ----------------
__device__ __half h_ln1 [MROWS*DD];
__device__ __half h_q   [MROWS*DD];
__device__ __half h_k   [MROWS*DD];
__device__ __half h_v   [MROWS*DD];
__device__ __half h_attn[MROWS*DD];
__device__ float  g_x1  [MROWS*DD];
__device__ __half h_ln2 [MROWS*DD];
__device__ __half h_ffn1[MROWS*DFF];
// transposed half weights: Wt[N][K]
__device__ __half h_wq[DD*DD];
__device__ __half h_wk[DD*DD];
__device__ __half h_wv[DD*DD];
__device__ __half h_wo[DD*DD];
__device__ __half h_w1[DD*DFF];
__device__ __half h_w2[DFF*DD];

// ---------------- helpers ----------------
__device__ __forceinline__ float gelu_exact(float v) {
    return 0.5f * v * (1.0f + erff(v * 0.70710678118654752f));
}
__device__ __forceinline__ void cp_async16(void* smem, const void* gmem) {
    uint32_t s = (uint32_t)__cvta_generic_to_shared(smem);
    asm volatile("cp.async.cg.shared.global [%0], [%1], 16;\n" :: "r"(s), "l"(gmem));
}
#define CP_COMMIT() asm volatile("cp.async.commit_group;\n" ::)
#define CP_WAIT(n)  asm volatile("cp.async.wait_group %0;\n" :: "n"(n))

__device__ __forceinline__ void mma_f16(float* c, const uint32_t* a, uint32_t b0, uint32_t b1) {
    asm volatile(
      "mma.sync.aligned.m16n8k16.row.col.f32.f16.f16.f32 "
      "{%0,%1,%2,%3}, {%4,%5,%6,%7}, {%8,%9}, {%0,%1,%2,%3};\n"
      : "+f"(c[0]), "+f"(c[1]), "+f"(c[2]), "+f"(c[3])
      : "r"(a[0]), "r"(a[1]), "r"(a[2]), "r"(a[3]), "r"(b0), "r"(b1));
}
__device__ __forceinline__ void ldsm_x4(uint32_t& r0, uint32_t& r1, uint32_t& r2, uint32_t& r3,
                                        uint32_t addr) {
    asm volatile("ldmatrix.sync.aligned.m8n8.x4.shared.b16 {%0,%1,%2,%3}, [%4];\n"
      : "=r"(r0), "=r"(r1), "=r"(r2), "=r"(r3) : "r"(addr));
}
__device__ __forceinline__ void ldsm_x4_t(uint32_t& r0, uint32_t& r1, uint32_t& r2, uint32_t& r3,
                                          uint32_t addr) {
    asm volatile("ldmatrix.sync.aligned.m8n8.x4.trans.shared.b16 {%0,%1,%2,%3}, [%4];\n"
      : "=r"(r0), "=r"(r1), "=r"(r2), "=r"(r3) : "r"(addr));
}

// ---------------- shared transpose-convert tile helper ----------------
__device__ __forceinline__ void wconv_tile(const float* __restrict__ W,
                                           __half* __restrict__ Wt,
                                           int K, int N, int tk, int tn,
                                           float* sb, int tid)
{
    const int k0 = tk * 32, n0 = tn * 32;
    const int tx = tid & 31, ty = tid >> 5;       // 32 x 8
    #pragma unroll
    for (int i = 0; i < 32; i += 8)
        sb[(ty + i) * 33 + tx] = W[(size_t)(k0 + ty + i) * N + n0 + tx];
    __syncthreads();
    #pragma unroll
    for (int i = 0; i < 32; i += 8)
        Wt[(size_t)(n0 + ty + i) * K + k0 + tx] = __float2half_rn(sb[tx * 33 + ty + i]);
}

// ---------------- prep: QKV weight transposes + LN1 ----------------
// blocks [0, 1728): wq/wk/wv 32x32 tiles; blocks [1728, 1728+MROWS): LN1 rows
__global__ void __launch_bounds__(256)
prep_kernel(const float* __restrict__ wq, const float* __restrict__ wk,
            const float* __restrict__ wv,
            __half* __restrict__ twq, __half* __restrict__ twk,
            __half* __restrict__ twv,
            const float* __restrict__ x, const float* __restrict__ gamma,
            const float* __restrict__ beta, __half* __restrict__ lnout)
{
    __shared__ float sb[32*33];
    const int idx = blockIdx.x;
    const int tid = threadIdx.x;

    if (idx < 1728) {
        const int which = idx / 576, r = idx % 576;
        const float* W  = (which == 0) ? wq  : (which == 1) ? wk  : wv;
        __half*      Wt = (which == 0) ? twq : (which == 1) ? twk : twv;
        wconv_tile(W, Wt, DD, DD, r % 24, r / 24, sb, tid);
    } else {
        const int row = idx - 1728;
        const float* xr = x + (size_t)row * DD;
        float a = xr[tid], b = xr[tid + 256], c = xr[tid + 512];
        float s  = a + b + c;
        float ss = a*a + b*b + c*c;
        #pragma unroll
        for (int off = 16; off > 0; off >>= 1) {
            s  += __shfl_xor_sync(0xffffffffu, s,  off);
            ss += __shfl_xor_sync(0xffffffffu, ss, off);
        }
        int wid = tid >> 5, lane = tid & 31;
        if (lane == 0) { sb[wid] = s; sb[8 + wid] = ss; }
        __syncthreads();
        float tot = 0.f, tot2 = 0.f;
        #pragma unroll
        for (int i = 0; i < 8; i++) { tot += sb[i]; tot2 += sb[8 + i]; }
        float mean = tot * (1.0f / DD);
        float var  = tot2 * (1.0f / DD) - mean * mean;
        float rstd = rsqrtf(var + 1e-7f);
        __half* orow = lnout + (size_t)row * DD;
        orow[tid      ] = __float2half_rn(gamma[tid      ] * (a - mean) * rstd + beta[tid      ]);
        orow[tid + 256] = __float2half_rn(gamma[tid + 256] * (b - mean) * rstd + beta[tid + 256]);
        orow[tid + 512] = __float2half_rn(gamma[tid + 512] * (c - mean) * rstd + beta[tid + 512]);
    }
}

// ---------------- LayerNorm (standalone, for LN2) ----------------
__global__ void ln_kernel(const float* __restrict__ x,
                          const float* __restrict__ gamma,
                          const float* __restrict__ beta,
                          __half* __restrict__ out)
{
    int row = blockIdx.x;
    const float* xr = x + (size_t)row * DD;
    int tid = threadIdx.x;

    float a = xr[tid], b = xr[tid + 256], c = xr[tid + 512];
    float s  = a + b + c;
    float ss = a*a + b*b + c*c;
    #pragma unroll
    for (int off = 16; off > 0; off >>= 1) {
        s  += __shfl_xor_sync(0xffffffffu, s,  off);
        ss += __shfl_xor_sync(0xffffffffu, ss, off);
    }
    __shared__ float sh0[8], sh1[8];
    int wid = tid >> 5, lane = tid & 31;
    if (lane == 0) { sh0[wid] = s; sh1[wid] = ss; }
    __syncthreads();
    float tot = 0.f, tot2 = 0.f;
    #pragma unroll
    for (int i = 0; i < 8; i++) { tot += sh0[i]; tot2 += sh1[i]; }
    float mean = tot * (1.0f / DD);
    float var  = tot2 * (1.0f / DD) - mean * mean;
    float rstd = rsqrtf(var + 1e-7f);

    __half* orow = out + (size_t)row * DD;
    orow[tid      ] = __float2half_rn(gamma[tid      ] * (a - mean) * rstd + beta[tid      ]);
    orow[tid + 256] = __float2half_rn(gamma[tid + 256] * (b - mean) * rstd + beta[tid + 256]);
    orow[tid + 512] = __float2half_rn(gamma[tid + 512] * (c - mean) * rstd + beta[tid + 512]);
}

// ---------------- fp16 tensor-core GEMM: templated BN, 4-stage ring -------
template<int EPI, int BN>
__device__ __forceinline__ void hgemm_body(
    const __half* __restrict__ A, const __half* __restrict__ Wt,
    const float* __restrict__ bias, const float* __restrict__ resid,
    void* __restrict__ Cv, int K, int N)
{
    constexpr int WN   = BN / 2;
    constexpr int NJ   = WN / 8;
    constexpr int JP   = WN / 16;
    constexpr int STG  = 10240 + BN * 80;

    extern __shared__ __align__(16) char dsm[];

    const int tid  = threadIdx.x;
    const int wid  = tid >> 5;
    const int lane = tid & 31;
    const int lr   = lane >> 2;
    const int lc   = lane & 3;
    const int wm   = wid >> 1;
    const int wn   = wid & 1;

    const int rowBase = blockIdx.y * 128;
    const int colBase = blockIdx.x * BN;

    float acc[4][NJ][4];
    #pragma unroll
    for (int i = 0; i < 4; i++)
        #pragma unroll
        for (int j = 0; j < NJ; j++)
            #pragma unroll
            for (int q = 0; q < 4; q++) acc[i][j][q] = 0.f;

    auto load_tiles = [&](int st, int k0) {
        __half (*As)[40] = (__half(*)[40])(dsm + st * STG);
        __half (*Bs)[40] = (__half(*)[40])(dsm + st * STG + 10240);
        #pragma unroll
        for (int i = 0; i < 4; i++) {
            int c = tid + i * 128;
            int r = c >> 2, ko = (c & 3) * 8;
            cp_async16(&As[r][ko], A + (size_t)(rowBase + r) * K + k0 + ko);
        }
        #pragma unroll
        for (int i = 0; i < BN / 32; i++) {
            int c = tid + i * 128;
            int r = c >> 2, ko = (c & 3) * 8;
            cp_async16(&Bs[r][ko], Wt + (size_t)(colBase + r) * K + k0 + ko);
        }
    };

    const int g = lane >> 3;
    const int grow = lane & 7;
    const int aRowOff = ((g & 1) * 8 + grow);
    const int aColOff = (g >> 1) * 8;
    const int bRowOff = ((g >> 1) * 8 + grow);
    const int bColOff = (g & 1) * 8;

    const int niter = K >> 5;
    load_tiles(0, 0);  CP_COMMIT();
    load_tiles(1, 32); CP_COMMIT();

    for (int it = 0; it < niter; it++) {
        const int st  = it & 3;
        const int pre = it + 2;
        if (pre < niter) {
            load_tiles(pre & 3, pre << 5);
            CP_COMMIT();
            CP_WAIT(2);
        } else if (it + 1 < niter) {
            CP_WAIT(1);
        } else {
            CP_WAIT(0);
        }
        __syncthreads();

        __half (*As)[40] = (__half(*)[40])(dsm + st * STG);
        __half (*Bs)[40] = (__half(*)[40])(dsm + st * STG + 10240);
        #pragma unroll
        for (int kc = 0; kc < 2; kc++) {
            const int kk = kc * 16;
            uint32_t bf[NJ][2];
            #pragma unroll
            for (int jp = 0; jp < JP; jp++) {
                const int n = wn * WN + jp * 16 + bRowOff;
                uint32_t addr = (uint32_t)__cvta_generic_to_shared(&Bs[n][kk + bColOff]);
                ldsm_x4(bf[2*jp][0], bf[2*jp][1], bf[2*jp+1][0], bf[2*jp+1][1], addr);
            }
            #pragma unroll
            for (int i = 0; i < 4; i++) {
                const int m = wm * 64 + i * 16;
                uint32_t a[4];
                uint32_t addr = (uint32_t)__cvta_generic_to_shared(&As[m + aRowOff][kk + aColOff]);
                ldsm_x4(a[0], a[1], a[2], a[3], addr);
                #pragma unroll
                for (int j = 0; j < NJ; j++) mma_f16(acc[i][j], a, bf[j][0], bf[j][1]);
            }
        }
    }

    const int row0 = rowBase + wm * 64;
    const int col0 = colBase + wn * WN;
    __half* Ch = (__half*)Cv;
    float*  Cf = (float*)Cv;
    #pragma unroll
    for (int j = 0; j < NJ; j++) {
        const int col = col0 + j * 8 + lc * 2;
        const float b0v = bias[col], b1v = bias[col + 1];
        #pragma unroll
        for (int i = 0; i < 4; i++) {
            const int r0 = row0 + i * 16 + lr;
            float v0 = acc[i][j][0] + b0v;
            float v1 = acc[i][j][1] + b1v;
            float v2 = acc[i][j][2] + b0v;
            float v3 = acc[i][j][3] + b1v;
            if (EPI == 1) {
                v0 += resid[(size_t)r0 * N + col];
                v1 += resid[(size_t)r0 * N + col + 1];
                v2 += resid[(size_t)(r0 + 8) * N + col];
                v3 += resid[(size_t)(r0 + 8) * N + col + 1];
                *(float2*)&Cf[(size_t)r0 * N + col]       = make_float2(v0, v1);
                *(float2*)&Cf[(size_t)(r0 + 8) * N + col] = make_float2(v2, v3);
            } else {
                if (EPI == 2) {
                    v0 = gelu_exact(v0); v1 = gelu_exact(v1);
                    v2 = gelu_exact(v2); v3 = gelu_exact(v3);
                }
                *(__half2*)&Ch[(size_t)r0 * N + col]       = __floats2half2_rn(v0, v1);
                *(__half2*)&Ch[(size_t)(r0 + 8) * N + col] = __floats2half2_rn(v2, v3);
            }
        }
    }
}

#define GSMEM_W (4*(10240+128*80))   // 81,920 B (BN=128)
#define GSMEM_N (4*(10240+64*80))    // 61,440 B (BN=64)

template<int EPI>
__global__ void __launch_bounds__(128, 2)
hgemmW(const __half* __restrict__ A, const __half* __restrict__ Wt,
       const float* __restrict__ bias, const float* __restrict__ resid,
       void* __restrict__ C, int K, int N)
{
    hgemm_body<EPI, 128>(A, Wt, bias, resid, C, K, N);
}

template<int EPI>
__global__ void __launch_bounds__(128, 3)
hgemmN(const __half* __restrict__ A, const __half* __restrict__ Wt,
       const float* __restrict__ bias, const float* __restrict__ resid,
       void* __restrict__ C, int K, int N)
{
    hgemm_body<EPI, 64>(A, Wt, bias, resid, C, K, N);
}

__global__ void __launch_bounds__(128, 2)
hgemm_qkv(const __half* __restrict__ A,
          const __half* __restrict__ wq, const __half* __restrict__ wk, const __half* __restrict__ wv,
          const float* __restrict__ bq, const float* __restrict__ bk, const float* __restrict__ bv,
          __half* __restrict__ qo, __half* __restrict__ ko, __half* __restrict__ vo,
          int K, int N)
{
    const __half* W  = (blockIdx.z == 0) ? wq : (blockIdx.z == 1) ? wk : wv;
    const float*  bi = (blockIdx.z == 0) ? bq : (blockIdx.z == 1) ? bk : bv;
    __half*       C  = (blockIdx.z == 0) ? qo : (blockIdx.z == 1) ? ko : vo;
    hgemm_body<0, 128>(A, W, bi, nullptr, C, K, N);
}

// ---------------- attention + riding wo/w1/w2 conversion ----------------
// 1D grid: blocks [0, 384) = causal flash attention (4-stage KV ring, exp2);
// blocks [384, 5568) = wo/w1/w2 transpose-convert tiles (fill attention tail).
#define AST 18432
#define ATTN_SMEM (4*AST)               // 73,728 B
#define ATTN_BLOCKS (BB*HH*(SS/128))    // 384
#define CONV_BLOCKS (576 + 2304 + 2304) // 5184

__global__ void __launch_bounds__(256)
attn_plus_kernel(const __half* __restrict__ q, const __half* __restrict__ k,
                 const __half* __restrict__ v, __half* __restrict__ o,
                 const float* __restrict__ wo, const float* __restrict__ w1,
                 const float* __restrict__ w2,
                 __half* __restrict__ two, __half* __restrict__ tw1,
                 __half* __restrict__ tw2)
{
    extern __shared__ __align__(16) char dsm[];
    const int tid = threadIdx.x;

    if (blockIdx.x >= ATTN_BLOCKS) {
        // ---- weight transpose-convert rider ----
        const int cid = blockIdx.x - ATTN_BLOCKS;
        float* sb = (float*)dsm;
        if (cid < 576) {
            wconv_tile(wo, two, DD, DD, cid % 24, cid / 24, sb, tid);
        } else if (cid < 2880) {
            const int r = cid - 576;
            wconv_tile(w1, tw1, DD, DFF, r % 24, r / 24, sb, tid);
        } else {
            const int r = cid - 2880;
            wconv_tile(w2, tw2, DFF, DD, r % 96, r / 96, sb, tid);
        }
        return;
    }

    // ---- attention ----
    const uint32_t smem_base = (uint32_t)__cvta_generic_to_shared(dsm);
    const int aid  = blockIdx.x;
    const int bh   = aid % (BB * HH);
    const int b    = bh / HH;
    const int h    = bh % HH;
    const int T    = (SS / 128 - 1) - (aid / (BB * HH));   // heavy tiles first
    const int q0   = T * 128;
    const int wid  = tid >> 5;
    const int lane = tid & 31;
    const int lr   = lane >> 2;
    const int lc   = lane & 3;
    const size_t headOff = (size_t)h * DKK;
    const size_t bBase   = (size_t)b * SS;

    {
        __half* Qst = (__half*)dsm;
        #pragma unroll
        for (int i = 0; i < 4; i++) {
            int c = tid + i * 256;
            int r = c >> 3, ko = (c & 7) * 8;
            *(uint4*)&Qst[r * 72 + ko] = *(const uint4*)(q + (bBase + q0 + r) * DD + headOff + ko);
        }
    }
    __syncthreads();

    // scale = log2(e)/sqrt(64): scores land in log2 domain
    const __half2 qscale = __half2half2(__float2half(0.18033688f));
    uint32_t qf[4][4];
    const int qrow = wid * 16;
    {
        const __half* Qst = (const __half*)dsm;
        #pragma unroll
        for (int kc = 0; kc < 4; kc++) {
            const int kk = kc * 16;
            __half2 t0 = *(__half2*)&Qst[(qrow + lr    ) * 72 + kk + lc * 2];
            __half2 t1 = *(__half2*)&Qst[(qrow + 8 + lr) * 72 + kk + lc * 2];
            __half2 t2 = *(__half2*)&Qst[(qrow + lr    ) * 72 + kk + 8 + lc * 2];
            __half2 t3 = *(__half2*)&Qst[(qrow + 8 + lr) * 72 + kk + 8 + lc * 2];
            t0 = __hmul2(t0, qscale); t1 = __hmul2(t1, qscale);
            t2 = __hmul2(t2, qscale); t3 = __hmul2(t3, qscale);
            qf[kc][0] = *(uint32_t*)&t0; qf[kc][1] = *(uint32_t*)&t1;
            qf[kc][2] = *(uint32_t*)&t2; qf[kc][3] = *(uint32_t*)&t3;
        }
    }
    __syncthreads();

    auto loadKV = [&](int st, int j0) {
        char* base = dsm + st * AST;
        #pragma unroll
        for (int i = 0; i < 2; i++) {
            int c = tid + i * 256;
            int r = c >> 3, ko = (c & 7) * 8;
            cp_async16(base        + (r * 72 + ko) * 2, k + (bBase + j0 + r) * DD + headOff + ko);
            cp_async16(base + 9216 + (r * 72 + ko) * 2, v + (bBase + j0 + r) * DD + headOff + ko);
        }
    };

    const int gq = lane >> 3, rr = lane & 7;
    const uint32_t vlane = ((uint32_t)(((gq & 1) * 8 + rr) * 72 + (gq >> 1) * 8)) * 2;
    const uint32_t klane = ((uint32_t)(((gq >> 1) * 8 + rr) * 72 + (gq & 1) * 8)) * 2;

    float oacc[8][4];
    #pragma unroll
    for (int nv = 0; nv < 8; nv++)
        #pragma unroll
        for (int t = 0; t < 4; t++) oacc[nv][t] = 0.f;
    float m0 = -1e30f, m1 = -1e30f, l0 = 0.f, l1 = 0.f;

    const int qglob0 = q0 + qrow;
    const int nkt = 2 * T + 2;

    loadKV(0, 0);  CP_COMMIT();
    loadKV(1, 64); CP_COMMIT();

    for (int kt = 0; kt < nkt; kt++) {
        const int st = kt & 3;
        const int j0 = kt * 64;
        if (kt + 2 < nkt) {
            loadKV((kt + 2) & 3, (kt + 2) * 64);
            CP_COMMIT();
            CP_WAIT(2);
        } else if (kt + 1 < nkt) {
            CP_WAIT(1);
        } else {
            CP_WAIT(0);
        }
        __syncthreads();

        if (j0 <= qglob0 + 15) {
            const uint32_t kb = smem_base + st * AST + klane;
            const uint32_t vb = smem_base + st * AST + 9216 + vlane;

            float sacc[8][4];
            #pragma unroll
            for (int nt = 0; nt < 8; nt++)
                sacc[nt][0] = sacc[nt][1] = sacc[nt][2] = sacc[nt][3] = 0.f;
            #pragma unroll
            for (int kc = 0; kc < 4; kc++) {
                #pragma unroll
                for (int np = 0; np < 4; np++) {
                    uint32_t b0, b1, b2, b3;
                    ldsm_x4(b0, b1, b2, b3, kb + np * 2304 + kc * 32);
                    mma_f16(sacc[2*np    ], qf[kc], b0, b1);
                    mma_f16(sacc[2*np + 1], qf[kc], b2, b3);
                }
            }

            if (j0 + 63 > qglob0) {
                const int qi0 = qglob0 + lr, qi1 = qi0 + 8;
                #pragma unroll
                for (int nt = 0; nt < 8; nt++) {
                    const int kj = j0 + nt * 8 + lc * 2;
                    if (kj     > qi0) sacc[nt][0] = -1e30f;
                    if (kj + 1 > qi0) sacc[nt][1] = -1e30f;
                    if (kj     > qi1) sacc[nt][2] = -1e30f;
                    if (kj + 1 > qi1) sacc[nt][3] = -1e30f;
                }
            }

            float mx0 = -1e30f, mx1 = -1e30f;
            #pragma unroll
            for (int nt = 0; nt < 8; nt++) {
                mx0 = fmaxf(mx0, fmaxf(sacc[nt][0], sacc[nt][1]));
                mx1 = fmaxf(mx1, fmaxf(sacc[nt][2], sacc[nt][3]));
            }
            mx0 = fmaxf(mx0, __shfl_xor_sync(0xffffffffu, mx0, 1));
            mx0 = fmaxf(mx0, __shfl_xor_sync(0xffffffffu, mx0, 2));
            mx1 = fmaxf(mx1, __shfl_xor_sync(0xffffffffu, mx1, 1));
            mx1 = fmaxf(mx1, __shfl_xor_sync(0xffffffffu, mx1, 2));

            const float mn0 = fmaxf(m0, mx0);
            const float mn1 = fmaxf(m1, mx1);
            const float sc0 = exp2f(m0 - mn0);
            const float sc1 = exp2f(m1 - mn1);
            m0 = mn0; m1 = mn1;

            float la0 = 0.f, la1 = 0.f;
            #pragma unroll
            for (int nt = 0; nt < 8; nt++) {
                sacc[nt][0] = exp2f(sacc[nt][0] - mn0);
                sacc[nt][1] = exp2f(sacc[nt][1] - mn0);
                sacc[nt][2] = exp2f(sacc[nt][2] - mn1);
                sacc[nt][3] = exp2f(sacc[nt][3] - mn1);
                la0 += sacc[nt][0] + sacc[nt][1];
                la1 += sacc[nt][2] + sacc[nt][3];
            }

            #pragma unroll
            for (int nv = 0; nv < 8; nv++) {
                oacc[nv][0] *= sc0; oacc[nv][1] *= sc0;
                oacc[nv][2] *= sc1; oacc[nv][3] *= sc1;
            }

            uint32_t pf[4][4];
            #pragma unroll
            for (int pk = 0; pk < 4; pk++) {
                __half2 h0 = __floats2half2_rn(sacc[2*pk    ][0], sacc[2*pk    ][1]);
                __half2 h1 = __floats2half2_rn(sacc[2*pk    ][2], sacc[2*pk    ][3]);
                __half2 h2 = __floats2half2_rn(sacc[2*pk + 1][0], sacc[2*pk + 1][1]);
                __half2 h3 = __floats2half2_rn(sacc[2*pk + 1][2], sacc[2*pk + 1][3]);
                pf[pk][0] = *(uint32_t*)&h0;
                pf[pk][1] = *(uint32_t*)&h1;
                pf[pk][2] = *(uint32_t*)&h2;
                pf[pk][3] = *(uint32_t*)&h3;
            }

            #pragma unroll
            for (int nh = 0; nh < 4; nh++) {
                #pragma unroll
                for (int pk = 0; pk < 4; pk++) {
                    uint32_t b0, b1, b2, b3;
                    ldsm_x4_t(b0, b1, b2, b3, vb + pk * 2304 + nh * 32);
                    mma_f16(oacc[2*nh    ], pf[pk], b0, b1);
                    mma_f16(oacc[2*nh + 1], pf[pk], b2, b3);
                }
            }

            la0 += __shfl_xor_sync(0xffffffffu, la0, 1);
            la0 += __shfl_xor_sync(0xffffffffu, la0, 2);
            la1 += __shfl_xor_sync(0xffffffffu, la1, 1);
            la1 += __shfl_xor_sync(0xffffffffu, la1, 2);
            l0 = l0 * sc0 + la0;
            l1 = l1 * sc1 + la1;
        }
    }

    const float inv0 = 1.f / l0;
    const float inv1 = 1.f / l1;
    const size_t r0 = bBase + q0 + qrow + lr;
    #pragma unroll
    for (int nv = 0; nv < 8; nv++) {
        const int col = nv * 8 + lc * 2;
        *(__half2*)&o[r0 * DD + headOff + col] =
            __floats2half2_rn(oacc[nv][0] * inv0, oacc[nv][1] * inv0);
        *(__half2*)&o[(r0 + 8) * DD + headOff + col] =
            __floats2half2_rn(oacc[nv][2] * inv1, oacc[nv][3] * inv1);
    }
}

// ---------------- host launcher ----------------
extern "C" void kernel_launch(void* const* d_in, const int* in_sizes, int n_in,
                              void* d_out, int out_size)
{
    const float* x    = (const float*)d_in[0];
    const float* ln1g = (const float*)d_in[1];
    const float* ln1b = (const float*)d_in[2];
    const float* wq   = (const float*)d_in[3];
    const float* bq   = (const float*)d_in[4];
    const float* wk   = (const float*)d_in[5];
    const float* bk   = (const float*)d_in[6];
    const float* wv   = (const float*)d_in[7];
    const float* bv   = (const float*)d_in[8];
    const float* wo   = (const float*)d_in[9];
    const float* bo   = (const float*)d_in[10];
    const float* ln2g = (const float*)d_in[11];
    const float* ln2b = (const float*)d_in[12];
    const float* w1   = (const float*)d_in[13];
    const float* b1   = (const float*)d_in[14];
    const float* w2   = (const float*)d_in[15];
    const float* b2   = (const float*)d_in[16];
    float* out = (float*)d_out;

    __half *ln1, *qb, *kb, *vb, *attn, *ln2, *ffn1;
    __half *twq, *twk, *twv, *two, *tw1, *tw2;
    float *x1;
    cudaGetSymbolAddress((void**)&ln1,  h_ln1);
    cudaGetSymbolAddress((void**)&qb,   h_q);
    cudaGetSymbolAddress((void**)&kb,   h_k);
    cudaGetSymbolAddress((void**)&vb,   h_v);
    cudaGetSymbolAddress((void**)&attn, h_attn);
    cudaGetSymbolAddress((void**)&x1,   g_x1);
    cudaGetSymbolAddress((void**)&ln2,  h_ln2);
    cudaGetSymbolAddress((void**)&ffn1, h_ffn1);
    cudaGetSymbolAddress((void**)&twq,  h_wq);
    cudaGetSymbolAddress((void**)&twk,  h_wk);
    cudaGetSymbolAddress((void**)&twv,  h_wv);
    cudaGetSymbolAddress((void**)&two,  h_wo);
    cudaGetSymbolAddress((void**)&tw1,  h_w1);
    cudaGetSymbolAddress((void**)&tw2,  h_w2);

    cudaFuncSetAttribute(hgemmW<0>, cudaFuncAttributeMaxDynamicSharedMemorySize, GSMEM_W);
    cudaFuncSetAttribute(hgemmW<2>, cudaFuncAttributeMaxDynamicSharedMemorySize, GSMEM_W);
    cudaFuncSetAttribute(hgemmN<1>, cudaFuncAttributeMaxDynamicSharedMemorySize, GSMEM_N);
    cudaFuncSetAttribute(hgemm_qkv, cudaFuncAttributeMaxDynamicSharedMemorySize, GSMEM_W);
    cudaFuncSetAttribute(attn_plus_kernel, cudaFuncAttributeMaxDynamicSharedMemorySize, ATTN_SMEM);

    // 0) prep: QKV weight converts + LN1
    prep_kernel<<<1728 + MROWS, 256>>>(wq, wk, wv, twq, twk, twv,
                                       x, ln1g, ln1b, ln1);

    // 1) QKV projections (wide tile, 576 CTAs)
    hgemm_qkv<<<dim3(DD / 128, MROWS / 128, 3), 128, GSMEM_W>>>(
        ln1, twq, twk, twv, bq, bk, bv, qb, kb, vb, DD, DD);

    // 2) causal attention + riding wo/w1/w2 conversion
    attn_plus_kernel<<<ATTN_BLOCKS + CONV_BLOCKS, 256, ATTN_SMEM>>>(
        qb, kb, vb, attn, wo, w1, w2, two, tw1, tw2);

    // 3) O projection + residual -> f32 x1 (narrow tile, 384 CTAs)
    hgemmN<1><<<dim3(DD / 64, MROWS / 128), 128, GSMEM_N>>>(attn, two, bo, x, x1, DD, DD);

    // 4) LN2 -> half
    ln_kernel<<<MROWS, 256>>>(x1, ln2g, ln2b, ln2);

    // 5) FFN up + GELU -> half (wide tile, 768 CTAs)
    hgemmW<2><<<dim3(DFF / 128, MROWS / 128), 128, GSMEM_W>>>(ln2, tw1, b1, nullptr, ffn1, DD, DFF);

    // 6) FFN down + residual -> f32 out (narrow tile, 384 CTAs)
    hgemmN<1><<<dim3(DD / 64, MROWS / 128), 128, GSMEM_N>>>(ffn1, tw2, b2, x1, out, DFF, DD);
}